// round 1
// baseline (speedup 1.0000x reference)
#include <cuda_runtime.h>
#include <cstdint>

// ---------------- problem constants ----------------
#define BATCH 16
#define C1    256     // input / output channels
#define CH    128     // hidden channels
#define HW    64      // H = W = 64
#define NPIX  (HW*HW) // 4096
#define INV_T (1.0f/16.0f)   // 1/sqrt(256)

// ---------------- scratch (device globals: allocation-free) ----------------
__device__ float g_y1[BATCH * CH * NPIX];        // 32 MB
__device__ float g_y2[BATCH * C1 * NPIX];        // 64 MB
__device__ float g_sc[BATCH * C1 * C1];          // 4 MB   scores / attn
__device__ float g_w1p[CH * C1 * 9];             // repacked weights conv1
__device__ float g_w2p[C1 * CH * 9];             // repacked weights conv2
__device__ float g_scale1[CH], g_shift1[CH];
__device__ float g_scale2[C1], g_shift2[C1];

// ---------------- BN fold ----------------
__global__ void fold_bn(const float* __restrict__ g1, const float* __restrict__ b1,
                        const float* __restrict__ m1, const float* __restrict__ v1,
                        const float* __restrict__ g2, const float* __restrict__ b2,
                        const float* __restrict__ m2, const float* __restrict__ v2)
{
    int i = threadIdx.x;
    if (i < CH) {
        float s = g1[i] * rsqrtf(v1[i] + 1e-5f);
        g_scale1[i] = s;
        g_shift1[i] = b1[i] - m1[i] * s;
    }
    if (i < C1) {
        float s = g2[i] * rsqrtf(v2[i] + 1e-5f);
        g_scale2[i] = s;
        g_shift2[i] = b2[i] - m2[i] * s;
    }
}

// ---------------- weight repack: [co][ci][t] -> [ci][t][co] ----------------
__global__ void repack_w(const float* __restrict__ w, float* __restrict__ wp,
                         int Cout, int Cin)
{
    int i = blockIdx.x * 256 + threadIdx.x;
    int total = Cout * Cin * 9;
    if (i < total) {
        int co = i / (Cin * 9);
        int ci = (i / 9) % Cin;
        int t  = i % 9;
        wp[(ci * 9 + t) * Cout + co] = w[i];
    }
}

// ---------------- conv 3x3 same + BN + SiLU ----------------
// Tile: 64 cout x 64 pixels (one full image row). Block 256 = (tx 0..15, ty 0..15).
// Thread computes 4 channels (ty*4..+3) x 4 pixels (tx*4..+3).
template<int CIN>
__global__ void __launch_bounds__(256)
conv3x3_bn_silu(const float* __restrict__ in, const float* __restrict__ wp,
                const float* __restrict__ scale, const float* __restrict__ shift,
                float* __restrict__ out, int Cout)
{
    const int b   = blockIdx.z;
    const int h   = blockIdx.y;
    const int co0 = blockIdx.x * 64;
    const int tid = threadIdx.x;
    const int ty  = tid >> 4;
    const int tx  = tid & 15;

    __shared__ float s_in[8][3][68];   // [ci][row][col: gw+1, 0..65 valid]
    __shared__ float s_w[8][9][64];    // [ci][tap][co]

    float4 accv[4];
    #pragma unroll
    for (int p = 0; p < 4; p++) accv[p] = make_float4(0.f, 0.f, 0.f, 0.f);

    const float* inb = in + (size_t)b * CIN * NPIX;

    for (int ci0 = 0; ci0 < CIN; ci0 += 8) {
        // ---- load input chunk (with zero halo) ----
        #pragma unroll
        for (int e = tid; e < 8 * 3 * 68; e += 256) {
            int ci  = e / 204;
            int rem = e % 204;
            int r   = rem / 68;
            int col = rem % 68;
            int gh = h + r - 1;
            int gw = col - 1;
            float v = 0.f;
            if ((unsigned)gh < (unsigned)HW && (unsigned)gw < (unsigned)HW && col < 66)
                v = inb[((ci0 + ci) * HW + gh) * HW + gw];
            s_in[ci][r][col] = v;
        }
        // ---- load weight chunk (coalesced from repacked layout) ----
        #pragma unroll
        for (int e = tid; e < 8 * 9 * 64; e += 256) {
            int ci  = e / 576;
            int rem = e % 576;
            int t   = rem / 64;
            int co  = rem % 64;
            s_w[ci][t][co] = wp[((size_t)(ci0 + ci) * 9 + t) * Cout + co0 + co];
        }
        __syncthreads();

        #pragma unroll
        for (int ci = 0; ci < 8; ci++) {
            float iv[3][6];
            #pragma unroll
            for (int r = 0; r < 3; r++) {
                float4 t0 = *(const float4*)&s_in[ci][r][tx * 4];
                float2 t1 = *(const float2*)&s_in[ci][r][tx * 4 + 4];
                iv[r][0] = t0.x; iv[r][1] = t0.y; iv[r][2] = t0.z; iv[r][3] = t0.w;
                iv[r][4] = t1.x; iv[r][5] = t1.y;
            }
            #pragma unroll
            for (int t = 0; t < 9; t++) {
                const int kh = t / 3, kw = t % 3;
                float4 w4 = *(const float4*)&s_w[ci][t][ty * 4];
                #pragma unroll
                for (int px = 0; px < 4; px++) {
                    float ivv = iv[kh][px + kw];
                    accv[px].x += ivv * w4.x;
                    accv[px].y += ivv * w4.y;
                    accv[px].z += ivv * w4.z;
                    accv[px].w += ivv * w4.w;
                }
            }
        }
        __syncthreads();
    }

    // ---- epilogue: BN + SiLU ----
    #pragma unroll
    for (int c = 0; c < 4; c++) {
        int co = co0 + ty * 4 + c;
        float sc = scale[co], sh = shift[co];
        #pragma unroll
        for (int px = 0; px < 4; px++) {
            float a = (c == 0) ? accv[px].x : (c == 1) ? accv[px].y : (c == 2) ? accv[px].z : accv[px].w;
            float y = a * sc + sh;
            y = y / (1.0f + __expf(-y));  // SiLU
            out[(((size_t)b * Cout + co) * HW + h) * HW + tx * 4 + px] = y;
        }
    }
}

// ---------------- gram: scores[b] = (Q/T) Q^T, Q = y2[b] [256 x 4096] ----------------
// tile 64x64, K chunk 32
__global__ void __launch_bounds__(256)
gram_kernel(const float* __restrict__ y2, float* __restrict__ sc)
{
    const int b  = blockIdx.z;
    const int c0 = blockIdx.y * 64;
    const int d0 = blockIdx.x * 64;
    const int tid = threadIdx.x;
    const int ty = tid >> 4, tx = tid & 15;

    __shared__ float As[32][68];
    __shared__ float Bs[32][68];

    float acc[4][4];
    #pragma unroll
    for (int i = 0; i < 4; i++)
        #pragma unroll
        for (int j = 0; j < 4; j++) acc[i][j] = 0.f;

    const float* Q = y2 + (size_t)b * C1 * NPIX;

    for (int nk = 0; nk < NPIX; nk += 32) {
        #pragma unroll
        for (int e = tid; e < 2048; e += 256) {
            int i = e >> 5, k = e & 31;
            As[k][i] = Q[(size_t)(c0 + i) * NPIX + nk + k];
        }
        #pragma unroll
        for (int e = tid; e < 2048; e += 256) {
            int i = e >> 5, k = e & 31;
            Bs[k][i] = Q[(size_t)(d0 + i) * NPIX + nk + k];
        }
        __syncthreads();

        #pragma unroll
        for (int kk = 0; kk < 32; kk++) {
            float4 a  = *(const float4*)&As[kk][ty * 4];
            float4 bv = *(const float4*)&Bs[kk][tx * 4];
            float av[4] = {a.x, a.y, a.z, a.w};
            float bb[4] = {bv.x, bv.y, bv.z, bv.w};
            #pragma unroll
            for (int i = 0; i < 4; i++)
                #pragma unroll
                for (int j = 0; j < 4; j++) acc[i][j] += av[i] * bb[j];
        }
        __syncthreads();
    }

    #pragma unroll
    for (int i = 0; i < 4; i++)
        #pragma unroll
        for (int j = 0; j < 4; j++) {
            int c = c0 + ty * 4 + i;
            int d = d0 + tx * 4 + j;
            sc[((size_t)b * C1 + c) * C1 + d] = acc[i][j] * INV_T;
        }
}

// ---------------- softmax over last dim (row length 256) ----------------
__global__ void __launch_bounds__(256)
softmax256(float* __restrict__ sc)
{
    const int row = blockIdx.x;
    const int t = threadIdx.x;
    __shared__ float red[256];

    float v = sc[(size_t)row * C1 + t];
    red[t] = v;
    __syncthreads();
    #pragma unroll
    for (int s = 128; s > 0; s >>= 1) {
        if (t < s) red[t] = fmaxf(red[t], red[t + s]);
        __syncthreads();
    }
    float m = red[0];
    __syncthreads();
    float e = __expf(v - m);
    red[t] = e;
    __syncthreads();
    #pragma unroll
    for (int s = 128; s > 0; s >>= 1) {
        if (t < s) red[t] += red[t + s];
        __syncthreads();
    }
    sc[(size_t)row * C1 + t] = e / red[0];
}

// ---------------- out[b] = attn[b] @ Q[b] + x ----------------
// M=256 (c), N=4096 (n), K=256 (d). tile 64x64, K chunk 32
__global__ void __launch_bounds__(256)
attn_out_kernel(const float* __restrict__ attn, const float* __restrict__ y2,
                const float* __restrict__ x, float* __restrict__ out)
{
    const int b  = blockIdx.z;
    const int c0 = blockIdx.y * 64;
    const int n0 = blockIdx.x * 64;
    const int tid = threadIdx.x;
    const int ty = tid >> 4, tx = tid & 15;

    __shared__ float As[32][68];   // [k][c]
    __shared__ float Bs[32][64];   // [k][n]

    float acc[4][4];
    #pragma unroll
    for (int i = 0; i < 4; i++)
        #pragma unroll
        for (int j = 0; j < 4; j++) acc[i][j] = 0.f;

    const float* A = attn + (size_t)b * C1 * C1;
    const float* Q = y2 + (size_t)b * C1 * NPIX;

    for (int dk = 0; dk < C1; dk += 32) {
        #pragma unroll
        for (int e = tid; e < 2048; e += 256) {
            int i = e >> 5, k = e & 31;
            As[k][i] = A[(size_t)(c0 + i) * C1 + dk + k];
        }
        #pragma unroll
        for (int e = tid; e < 2048; e += 256) {
            int k = e >> 6, j = e & 63;
            Bs[k][j] = Q[(size_t)(dk + k) * NPIX + n0 + j];
        }
        __syncthreads();

        #pragma unroll
        for (int kk = 0; kk < 32; kk++) {
            float4 a  = *(const float4*)&As[kk][ty * 4];
            float4 bv = *(const float4*)&Bs[kk][tx * 4];
            float av[4] = {a.x, a.y, a.z, a.w};
            float bb[4] = {bv.x, bv.y, bv.z, bv.w};
            #pragma unroll
            for (int i = 0; i < 4; i++)
                #pragma unroll
                for (int j = 0; j < 4; j++) acc[i][j] += av[i] * bb[j];
        }
        __syncthreads();
    }

    #pragma unroll
    for (int i = 0; i < 4; i++)
        #pragma unroll
        for (int j = 0; j < 4; j++) {
            size_t idx = ((size_t)b * C1 + c0 + ty * 4 + i) * NPIX + n0 + tx * 4 + j;
            out[idx] = acc[i][j] + x[idx];
        }
}

// ---------------- launch ----------------
extern "C" void kernel_launch(void* const* d_in, const int* in_sizes, int n_in,
                              void* d_out, int out_size)
{
    const float* x  = (const float*)d_in[0];
    const float* w1 = (const float*)d_in[1];
    const float* g1 = (const float*)d_in[2];
    const float* b1 = (const float*)d_in[3];
    const float* m1 = (const float*)d_in[4];
    const float* v1 = (const float*)d_in[5];
    const float* w2 = (const float*)d_in[6];
    const float* g2 = (const float*)d_in[7];
    const float* b2 = (const float*)d_in[8];
    const float* m2 = (const float*)d_in[9];
    const float* v2 = (const float*)d_in[10];
    float* out = (float*)d_out;

    float *y1p, *y2p, *scp, *w1p, *w2p, *sc1p, *sh1p, *sc2p, *sh2p;
    cudaGetSymbolAddress((void**)&y1p,  g_y1);
    cudaGetSymbolAddress((void**)&y2p,  g_y2);
    cudaGetSymbolAddress((void**)&scp,  g_sc);
    cudaGetSymbolAddress((void**)&w1p,  g_w1p);
    cudaGetSymbolAddress((void**)&w2p,  g_w2p);
    cudaGetSymbolAddress((void**)&sc1p, g_scale1);
    cudaGetSymbolAddress((void**)&sh1p, g_shift1);
    cudaGetSymbolAddress((void**)&sc2p, g_scale2);
    cudaGetSymbolAddress((void**)&sh2p, g_shift2);

    fold_bn<<<1, 256>>>(g1, b1, m1, v1, g2, b2, m2, v2);

    int nw1 = CH * C1 * 9;
    repack_w<<<(nw1 + 255) / 256, 256>>>(w1, w1p, CH, C1);
    repack_w<<<(nw1 + 255) / 256, 256>>>(w2, w2p, C1, CH);

    conv3x3_bn_silu<C1><<<dim3(CH / 64, HW, BATCH), 256>>>(x,   w1p, sc1p, sh1p, y1p, CH);
    conv3x3_bn_silu<CH><<<dim3(C1 / 64, HW, BATCH), 256>>>(y1p, w2p, sc2p, sh2p, y2p, C1);

    gram_kernel<<<dim3(C1 / 64, C1 / 64, BATCH), 256>>>(y2p, scp);
    softmax256<<<BATCH * C1, 256>>>(scp);
    attn_out_kernel<<<dim3(NPIX / 64, C1 / 64, BATCH), 256>>>(scp, y2p, x, out);
}

// round 3
// speedup vs baseline: 1.6752x; 1.6752x over previous
#include <cuda_runtime.h>
#include <cstdint>

// ---------------- problem constants ----------------
#define BATCH 16
#define C1    256
#define CH    128
#define HW    64
#define NPIX  (HW*HW)
#define INV_T (1.0f/16.0f)

// ---------------- scratch ----------------
__device__ float g_y1[BATCH * CH * NPIX];
__device__ float g_y2[BATCH * C1 * NPIX];
__device__ float g_sc[BATCH * C1 * C1];
__device__ float g_w1p[CH * C1 * 9];      // tf32-bit weights, [ci][tap][co]
__device__ float g_w2p[C1 * CH * 9];
__device__ float g_scale1[CH], g_shift1[CH];
__device__ float g_scale2[C1], g_shift2[C1];

// ---------------- tf32 helpers ----------------
__device__ __forceinline__ uint32_t f2tf32(float f) {
    uint32_t u;
    asm("cvt.rna.tf32.f32 %0, %1;" : "=r"(u) : "f"(f));
    return u;
}

__device__ __forceinline__ void mma_tf32(float c[4], const uint32_t a[4],
                                         uint32_t b0, uint32_t b1) {
    asm volatile(
        "mma.sync.aligned.m16n8k8.row.col.f32.tf32.tf32.f32 "
        "{%0,%1,%2,%3}, {%4,%5,%6,%7}, {%8,%9}, {%0,%1,%2,%3};"
        : "+f"(c[0]), "+f"(c[1]), "+f"(c[2]), "+f"(c[3])
        : "r"(a[0]), "r"(a[1]), "r"(a[2]), "r"(a[3]), "r"(b0), "r"(b1));
}

__device__ __forceinline__ float silu(float y) {
    return y / (1.0f + __expf(-y));
}

// ---------------- BN fold ----------------
__global__ void fold_bn(const float* __restrict__ g1, const float* __restrict__ b1,
                        const float* __restrict__ m1, const float* __restrict__ v1,
                        const float* __restrict__ g2, const float* __restrict__ b2,
                        const float* __restrict__ m2, const float* __restrict__ v2)
{
    int i = threadIdx.x;
    if (i < CH) {
        float s = g1[i] * rsqrtf(v1[i] + 1e-5f);
        g_scale1[i] = s;
        g_shift1[i] = b1[i] - m1[i] * s;
    }
    if (i < C1) {
        float s = g2[i] * rsqrtf(v2[i] + 1e-5f);
        g_scale2[i] = s;
        g_shift2[i] = b2[i] - m2[i] * s;
    }
}

// ---------------- weight repack: [co][ci][t] -> [ci][t][co], tf32 bits ----------------
__global__ void repack_w(const float* __restrict__ w, float* __restrict__ wp,
                         int Cout, int Cin)
{
    int i = blockIdx.x * 256 + threadIdx.x;
    int total = Cout * Cin * 9;
    if (i < total) {
        int co = i / (Cin * 9);
        int ci = (i / 9) % Cin;
        int t  = i % 9;
        wp[(ci * 9 + t) * Cout + co] = __uint_as_float(f2tf32(w[i]));
    }
}

// ---------------- conv 3x3 same + BN + SiLU  (tf32 mma implicit GEMM) ----------------
// Block tile: 64 cout x (2 rows x 64 px). 8 warps: wid bit0->co half, bit1->row, bit2->px half.
// Warp tile: 32 cout x 32 px => 2 m-tiles x 4 n-tiles of m16n8k8.
template<int CIN>
__global__ void __launch_bounds__(256)
conv3x3_mma(const float* __restrict__ in, const float* __restrict__ wp,
            const float* __restrict__ scale, const float* __restrict__ shift,
            float* __restrict__ out, int Cout)
{
    const int b   = blockIdx.z;
    const int h0  = blockIdx.y * 2;
    const int co0 = blockIdx.x * 64;
    const int tid  = threadIdx.x;
    const int wid  = tid >> 5;
    const int lane = tid & 31;
    const int g  = lane >> 2;
    const int tg = lane & 3;
    const int co_w = (wid & 1) * 32;
    const int r_w  = (wid >> 1) & 1;
    const int px0  = (wid >> 2) * 32;

    // row strides chosen so fragment-load banks = 8*tg + g (conflict-free)
    __shared__ uint32_t s_in[8 * 4 * 74];   // [ci][row(4: h0-1..h0+2)][col(74, 0..65 valid)]
    __shared__ uint32_t s_w[9 * 8 * 72];    // [(tap*8+ci)][co(72, 0..63 valid)]

    float acc[2][4][4];
    #pragma unroll
    for (int mt = 0; mt < 2; mt++)
        #pragma unroll
        for (int nt = 0; nt < 4; nt++)
            #pragma unroll
            for (int r = 0; r < 4; r++) acc[mt][nt][r] = 0.f;

    const float* inb = in + (size_t)b * CIN * NPIX;

    for (int ci0 = 0; ci0 < CIN; ci0 += 8) {
        // ---- input chunk (tf32 in smem, zero halo) ----
        for (int e = tid; e < 8 * 4 * 74; e += 256) {
            int ci  = e / 296;
            int rem = e % 296;
            int r   = rem / 74;
            int col = rem % 74;
            if (col < 66) {
                int gh = h0 + r - 1;
                int gw = col - 1;
                float v = 0.f;
                if ((unsigned)gh < (unsigned)HW && (unsigned)gw < (unsigned)HW)
                    v = inb[((ci0 + ci) * HW + gh) * HW + gw];
                s_in[(ci * 4 + r) * 74 + col] = f2tf32(v);
            }
        }
        // ---- weight chunk (already tf32 bits) ----
        for (int e = tid; e < 8 * 9 * 64; e += 256) {
            int ci = e / 576;
            int t  = (e % 576) / 64;
            int co = e % 64;
            s_w[(t * 8 + ci) * 72 + co] =
                __float_as_uint(wp[((size_t)(ci0 + ci) * 9 + t) * Cout + co0 + co]);
        }
        __syncthreads();

        #pragma unroll
        for (int t = 0; t < 9; t++) {
            const int kh = t / 3, kw = t % 3;
            uint32_t a[2][4];
            #pragma unroll
            for (int mt = 0; mt < 2; mt++) {
                int base = co_w + mt * 16;
                a[mt][0] = s_w[(t * 8 + tg) * 72 + base + g];
                a[mt][1] = s_w[(t * 8 + tg) * 72 + base + g + 8];
                a[mt][2] = s_w[(t * 8 + tg + 4) * 72 + base + g];
                a[mt][3] = s_w[(t * 8 + tg + 4) * 72 + base + g + 8];
            }
            const int rr = r_w + kh;
            #pragma unroll
            for (int nt = 0; nt < 4; nt++) {
                int col = px0 + nt * 8 + g + kw;
                uint32_t b0 = s_in[(tg * 4 + rr) * 74 + col];
                uint32_t b1 = s_in[((tg + 4) * 4 + rr) * 74 + col];
                mma_tf32(acc[0][nt], a[0], b0, b1);
                mma_tf32(acc[1][nt], a[1], b0, b1);
            }
        }
        __syncthreads();
    }

    // ---- epilogue: BN + SiLU, float2 stores ----
    const int h = h0 + r_w;
    #pragma unroll
    for (int mt = 0; mt < 2; mt++) {
        int coA = co0 + co_w + mt * 16 + g;
        int coB = coA + 8;
        float scA = scale[coA], shA = shift[coA];
        float scB = scale[coB], shB = shift[coB];
        float* rowA = out + (((size_t)b * Cout + coA) * HW + h) * HW;
        float* rowB = out + (((size_t)b * Cout + coB) * HW + h) * HW;
        #pragma unroll
        for (int nt = 0; nt < 4; nt++) {
            int px = px0 + nt * 8 + tg * 2;
            float2 vA, vB;
            vA.x = silu(acc[mt][nt][0] * scA + shA);
            vA.y = silu(acc[mt][nt][1] * scA + shA);
            vB.x = silu(acc[mt][nt][2] * scB + shB);
            vB.y = silu(acc[mt][nt][3] * scB + shB);
            *(float2*)&rowA[px] = vA;
            *(float2*)&rowB[px] = vB;
        }
    }
}

// ---------------- gram: scores[b] = (Q/T) Q^T  (tf32 mma) ----------------
// Block tile 64c x 64d, k-chunk 32. 8 warps: warp tile 32c x 16d.
__global__ void __launch_bounds__(256)
gram_mma(const float* __restrict__ y2, float* __restrict__ sc)
{
    const int b  = blockIdx.z;
    const int c0 = blockIdx.y * 64;
    const int d0 = blockIdx.x * 64;
    const int tid  = threadIdx.x;
    const int wid  = tid >> 5;
    const int lane = tid & 31;
    const int g  = lane >> 2;
    const int tg = lane & 3;
    const int m_w = (wid & 1) * 32;
    const int n_w = (wid >> 1) * 16;

    __shared__ uint32_t sA[32 * 72];   // [k][c]
    __shared__ uint32_t sB[32 * 72];   // [k][d]

    float acc[2][2][4];
    #pragma unroll
    for (int mt = 0; mt < 2; mt++)
        #pragma unroll
        for (int nt = 0; nt < 2; nt++)
            #pragma unroll
            for (int r = 0; r < 4; r++) acc[mt][nt][r] = 0.f;

    const float* Q = y2 + (size_t)b * C1 * NPIX;

    for (int nk = 0; nk < NPIX; nk += 32) {
        #pragma unroll
        for (int e = tid; e < 512; e += 256) {
            int i = e >> 3, kq = (e & 7) * 4;
            float4 v = *(const float4*)&Q[(size_t)(c0 + i) * NPIX + nk + kq];
            sA[(kq + 0) * 72 + i] = f2tf32(v.x);
            sA[(kq + 1) * 72 + i] = f2tf32(v.y);
            sA[(kq + 2) * 72 + i] = f2tf32(v.z);
            sA[(kq + 3) * 72 + i] = f2tf32(v.w);
        }
        #pragma unroll
        for (int e = tid; e < 512; e += 256) {
            int i = e >> 3, kq = (e & 7) * 4;
            float4 v = *(const float4*)&Q[(size_t)(d0 + i) * NPIX + nk + kq];
            sB[(kq + 0) * 72 + i] = f2tf32(v.x);
            sB[(kq + 1) * 72 + i] = f2tf32(v.y);
            sB[(kq + 2) * 72 + i] = f2tf32(v.z);
            sB[(kq + 3) * 72 + i] = f2tf32(v.w);
        }
        __syncthreads();

        #pragma unroll
        for (int ks = 0; ks < 4; ks++) {
            int kb = ks * 8;
            uint32_t a[2][4];
            #pragma unroll
            for (int mt = 0; mt < 2; mt++) {
                int base = m_w + mt * 16;
                a[mt][0] = sA[(kb + tg) * 72 + base + g];
                a[mt][1] = sA[(kb + tg) * 72 + base + g + 8];
                a[mt][2] = sA[(kb + tg + 4) * 72 + base + g];
                a[mt][3] = sA[(kb + tg + 4) * 72 + base + g + 8];
            }
            #pragma unroll
            for (int nt = 0; nt < 2; nt++) {
                uint32_t b0 = sB[(kb + tg) * 72 + n_w + nt * 8 + g];
                uint32_t b1 = sB[(kb + tg + 4) * 72 + n_w + nt * 8 + g];
                mma_tf32(acc[0][nt], a[0], b0, b1);
                mma_tf32(acc[1][nt], a[1], b0, b1);
            }
        }
        __syncthreads();
    }

    #pragma unroll
    for (int mt = 0; mt < 2; mt++) {
        int cA = c0 + m_w + mt * 16 + g;
        int cB = cA + 8;
        #pragma unroll
        for (int nt = 0; nt < 2; nt++) {
            int d = d0 + n_w + nt * 8 + tg * 2;
            float2 vA = make_float2(acc[mt][nt][0] * INV_T, acc[mt][nt][1] * INV_T);
            float2 vB = make_float2(acc[mt][nt][2] * INV_T, acc[mt][nt][3] * INV_T);
            *(float2*)&sc[((size_t)b * C1 + cA) * C1 + d] = vA;
            *(float2*)&sc[((size_t)b * C1 + cB) * C1 + d] = vB;
        }
    }
}

// ---------------- softmax over rows of length 256 ----------------
__global__ void __launch_bounds__(256)
softmax256(float* __restrict__ sc)
{
    const int row = blockIdx.x;
    const int t = threadIdx.x;
    __shared__ float red[256];

    float v = sc[(size_t)row * C1 + t];
    red[t] = v;
    __syncthreads();
    #pragma unroll
    for (int s = 128; s > 0; s >>= 1) {
        if (t < s) red[t] = fmaxf(red[t], red[t + s]);
        __syncthreads();
    }
    float m = red[0];
    __syncthreads();
    float e = __expf(v - m);
    red[t] = e;
    __syncthreads();
    #pragma unroll
    for (int s = 128; s > 0; s >>= 1) {
        if (t < s) red[t] += red[t + s];
        __syncthreads();
    }
    sc[(size_t)row * C1 + t] = e / red[0];
}

// ---------------- out[b] = attn[b] @ Q[b] + x  (tf32 mma) ----------------
// M=256(c), N=4096(n), K=256(d). Block tile 64c x 64n.
__global__ void __launch_bounds__(256)
attn_out_mma(const float* __restrict__ attn, const float* __restrict__ y2,
             const float* __restrict__ x, float* __restrict__ out)
{
    const int b  = blockIdx.z;
    const int c0 = blockIdx.y * 64;
    const int n0 = blockIdx.x * 64;
    const int tid  = threadIdx.x;
    const int wid  = tid >> 5;
    const int lane = tid & 31;
    const int g  = lane >> 2;
    const int tg = lane & 3;
    const int m_w = (wid & 1) * 32;
    const int n_w = (wid >> 1) * 16;

    __shared__ uint32_t sA[32 * 72];   // [k][c]
    __shared__ uint32_t sB[32 * 72];   // [k][n]

    float acc[2][2][4];
    #pragma unroll
    for (int mt = 0; mt < 2; mt++)
        #pragma unroll
        for (int nt = 0; nt < 2; nt++)
            #pragma unroll
            for (int r = 0; r < 4; r++) acc[mt][nt][r] = 0.f;

    const float* A = attn + (size_t)b * C1 * C1;
    const float* Q = y2 + (size_t)b * C1 * NPIX;

    for (int dk = 0; dk < C1; dk += 32) {
        #pragma unroll
        for (int e = tid; e < 512; e += 256) {
            int i = e >> 3, kq = (e & 7) * 4;
            float4 v = *(const float4*)&A[(size_t)(c0 + i) * C1 + dk + kq];
            sA[(kq + 0) * 72 + i] = f2tf32(v.x);
            sA[(kq + 1) * 72 + i] = f2tf32(v.y);
            sA[(kq + 2) * 72 + i] = f2tf32(v.z);
            sA[(kq + 3) * 72 + i] = f2tf32(v.w);
        }
        #pragma unroll
        for (int e = tid; e < 512; e += 256) {
            int k = e >> 4, j = (e & 15) * 4;
            float4 v = *(const float4*)&Q[(size_t)(dk + k) * NPIX + n0 + j];
            uint4 u;
            u.x = f2tf32(v.x); u.y = f2tf32(v.y);
            u.z = f2tf32(v.z); u.w = f2tf32(v.w);
            *(uint4*)&sB[k * 72 + j] = u;
        }
        __syncthreads();

        #pragma unroll
        for (int ks = 0; ks < 4; ks++) {
            int kb = ks * 8;
            uint32_t a[2][4];
            #pragma unroll
            for (int mt = 0; mt < 2; mt++) {
                int base = m_w + mt * 16;
                a[mt][0] = sA[(kb + tg) * 72 + base + g];
                a[mt][1] = sA[(kb + tg) * 72 + base + g + 8];
                a[mt][2] = sA[(kb + tg + 4) * 72 + base + g];
                a[mt][3] = sA[(kb + tg + 4) * 72 + base + g + 8];
            }
            #pragma unroll
            for (int nt = 0; nt < 2; nt++) {
                uint32_t b0 = sB[(kb + tg) * 72 + n_w + nt * 8 + g];
                uint32_t b1 = sB[(kb + tg + 4) * 72 + n_w + nt * 8 + g];
                mma_tf32(acc[0][nt], a[0], b0, b1);
                mma_tf32(acc[1][nt], a[1], b0, b1);
            }
        }
        __syncthreads();
    }

    #pragma unroll
    for (int mt = 0; mt < 2; mt++) {
        int cA = c0 + m_w + mt * 16 + g;
        int cB = cA + 8;
        #pragma unroll
        for (int nt = 0; nt < 2; nt++) {
            int n = n0 + n_w + nt * 8 + tg * 2;
            size_t iA = ((size_t)b * C1 + cA) * NPIX + n;
            size_t iB = ((size_t)b * C1 + cB) * NPIX + n;
            float2 xA = *(const float2*)&x[iA];
            float2 xB = *(const float2*)&x[iB];
            float2 vA = make_float2(acc[mt][nt][0] + xA.x, acc[mt][nt][1] + xA.y);
            float2 vB = make_float2(acc[mt][nt][2] + xB.x, acc[mt][nt][3] + xB.y);
            *(float2*)&out[iA] = vA;
            *(float2*)&out[iB] = vB;
        }
    }
}

// ---------------- launch ----------------
extern "C" void kernel_launch(void* const* d_in, const int* in_sizes, int n_in,
                              void* d_out, int out_size)
{
    const float* x  = (const float*)d_in[0];
    const float* w1 = (const float*)d_in[1];
    const float* g1 = (const float*)d_in[2];
    const float* b1 = (const float*)d_in[3];
    const float* m1 = (const float*)d_in[4];
    const float* v1 = (const float*)d_in[5];
    const float* w2 = (const float*)d_in[6];
    const float* g2 = (const float*)d_in[7];
    const float* b2 = (const float*)d_in[8];
    const float* m2 = (const float*)d_in[9];
    const float* v2 = (const float*)d_in[10];
    float* out = (float*)d_out;

    float *y1p, *y2p, *scp, *w1p, *w2p, *sc1p, *sh1p, *sc2p, *sh2p;
    cudaGetSymbolAddress((void**)&y1p,  g_y1);
    cudaGetSymbolAddress((void**)&y2p,  g_y2);
    cudaGetSymbolAddress((void**)&scp,  g_sc);
    cudaGetSymbolAddress((void**)&w1p,  g_w1p);
    cudaGetSymbolAddress((void**)&w2p,  g_w2p);
    cudaGetSymbolAddress((void**)&sc1p, g_scale1);
    cudaGetSymbolAddress((void**)&sh1p, g_shift1);
    cudaGetSymbolAddress((void**)&sc2p, g_scale2);
    cudaGetSymbolAddress((void**)&sh2p, g_shift2);

    fold_bn<<<1, 256>>>(g1, b1, m1, v1, g2, b2, m2, v2);

    int nw1 = CH * C1 * 9;
    repack_w<<<(nw1 + 255) / 256, 256>>>(w1, w1p, CH, C1);
    repack_w<<<(nw1 + 255) / 256, 256>>>(w2, w2p, C1, CH);

    conv3x3_mma<C1><<<dim3(CH / 64, HW / 2, BATCH), 256>>>(x,   w1p, sc1p, sh1p, y1p, CH);
    conv3x3_mma<CH><<<dim3(C1 / 64, HW / 2, BATCH), 256>>>(y1p, w2p, sc2p, sh2p, y2p, C1);

    gram_mma<<<dim3(C1 / 64, C1 / 64, BATCH), 256>>>(y2p, scp);
    softmax256<<<BATCH * C1, 256>>>(scp);
    attn_out_mma<<<dim3(NPIX / 64, C1 / 64, BATCH), 256>>>(scp, y2p, x, out);
}

// round 4
// speedup vs baseline: 2.8701x; 1.7133x over previous
#include <cuda_runtime.h>
#include <cstdint>

// ---------------- problem constants ----------------
#define BATCH 16
#define C1    256
#define CH    128
#define HW    64
#define NPIX  (HW*HW)
#define INV_T (1.0f/16.0f)

// ---------------- scratch ----------------
__device__ uint32_t g_xt[BATCH * C1 * NPIX];   // x as tf32 bits
__device__ uint32_t g_y1[BATCH * CH * NPIX];   // y1 as tf32 bits
__device__ uint32_t g_y2[BATCH * C1 * NPIX];   // y2 as tf32 bits
__device__ float    g_sc[BATCH * C1 * C1];     // scores / attn (fp32)
__device__ float    g_w1p[CH * C1 * 9];        // tf32-bit weights [ci][tap][co]
__device__ float    g_w2p[C1 * CH * 9];
__device__ float    g_scale1[CH], g_shift1[CH];
__device__ float    g_scale2[C1], g_shift2[C1];

__constant__ int c_ti[10] = {0,0,0,0,1,1,1,2,2,3};
__constant__ int c_tj[10] = {0,1,2,3,1,2,3,2,3,3};

// ---------------- helpers ----------------
__device__ __forceinline__ uint32_t f2tf32(float f) {
    uint32_t u;
    asm("cvt.rna.tf32.f32 %0, %1;" : "=r"(u) : "f"(f));
    return u;
}

__device__ __forceinline__ void mma_tf32(float c[4], const uint32_t a[4],
                                         uint32_t b0, uint32_t b1) {
    asm volatile(
        "mma.sync.aligned.m16n8k8.row.col.f32.tf32.tf32.f32 "
        "{%0,%1,%2,%3}, {%4,%5,%6,%7}, {%8,%9}, {%0,%1,%2,%3};"
        : "+f"(c[0]), "+f"(c[1]), "+f"(c[2]), "+f"(c[3])
        : "r"(a[0]), "r"(a[1]), "r"(a[2]), "r"(a[3]), "r"(b0), "r"(b1));
}

__device__ __forceinline__ float silu(float y) {
    return y / (1.0f + __expf(-y));
}

// ---------------- BN fold ----------------
__global__ void fold_bn(const float* __restrict__ g1, const float* __restrict__ b1,
                        const float* __restrict__ m1, const float* __restrict__ v1,
                        const float* __restrict__ g2, const float* __restrict__ b2,
                        const float* __restrict__ m2, const float* __restrict__ v2)
{
    int i = threadIdx.x;
    if (i < CH) {
        float s = g1[i] * rsqrtf(v1[i] + 1e-5f);
        g_scale1[i] = s;
        g_shift1[i] = b1[i] - m1[i] * s;
    }
    if (i < C1) {
        float s = g2[i] * rsqrtf(v2[i] + 1e-5f);
        g_scale2[i] = s;
        g_shift2[i] = b2[i] - m2[i] * s;
    }
}

// ---------------- weight repack: [co][ci][t] -> [ci][t][co], tf32 bits ----------------
__global__ void repack_w(const float* __restrict__ w, float* __restrict__ wp,
                         int Cout, int Cin)
{
    int i = blockIdx.x * 256 + threadIdx.x;
    int total = Cout * Cin * 9;
    if (i < total) {
        int co = i / (Cin * 9);
        int ci = (i / 9) % Cin;
        int t  = i % 9;
        wp[(ci * 9 + t) * Cout + co] = __uint_as_float(f2tf32(w[i]));
    }
}

// ---------------- bulk fp32 -> tf32 bits ----------------
__global__ void cvt_to_tf32(const float4* __restrict__ src, uint4* __restrict__ dst, int n4)
{
    int i = blockIdx.x * 256 + threadIdx.x;
    if (i < n4) {
        float4 v = src[i];
        uint4 u;
        u.x = f2tf32(v.x); u.y = f2tf32(v.y);
        u.z = f2tf32(v.z); u.w = f2tf32(v.w);
        dst[i] = u;
    }
}

// ---------------- conv 3x3 same + BN + SiLU  (tf32 mma implicit GEMM) ----------------
// Block: 64 cout x 4 rows x 64 px. 8 warps: wid&1 -> co half, wid>>1 -> row.
// Warp tile: 32 cout x 64 px = 2 m-tiles x 8 n-tiles of m16n8k8. K-chunk = 8 cin.
template<int CIN>
__global__ void __launch_bounds__(256)
conv3x3_mma(const uint32_t* __restrict__ in, const float* __restrict__ wp,
            const float* __restrict__ scale, const float* __restrict__ shift,
            uint32_t* __restrict__ out, int Cout)
{
    const int b   = blockIdx.z;
    const int h0  = blockIdx.y * 4;
    const int co0 = blockIdx.x * 64;
    const int tid  = threadIdx.x;
    const int wid  = tid >> 5;
    const int lane = tid & 31;
    const int g  = lane >> 2;
    const int tg = lane & 3;
    const int co_w = (wid & 1) * 32;
    const int r_w  = wid >> 1;          // 0..3

    __shared__ uint32_t s_in[6 * 8 * 72];   // [(r*8+ci)*72 + c], c = gw+1 (0..65 valid)
    __shared__ uint32_t s_w[9 * 8 * 72];    // [(t*8+ci)*72 + co]

    float acc[2][8][4];
    #pragma unroll
    for (int mt = 0; mt < 2; mt++)
        #pragma unroll
        for (int nt = 0; nt < 8; nt++)
            #pragma unroll
            for (int r = 0; r < 4; r++) acc[mt][nt][r] = 0.f;

    // halo columns 0 and 65 are always zero
    if (tid < 96) {
        int ridx = tid >> 1;
        s_in[ridx * 72 + ((tid & 1) ? 65 : 0)] = 0;
    }

    const uint32_t* inb = in + (size_t)b * CIN * NPIX;
    const int lrow = tid >> 6;   // 0..3
    const int lcol = tid & 63;   // 0..63

    for (int ci0 = 0; ci0 < CIN; ci0 += 8) {
        // ---- input chunk: 48 rows (r*8+ci) x cols 1..64 ----
        #pragma unroll
        for (int p = 0; p < 12; p++) {
            int ridx = p * 4 + lrow;          // 0..47
            int r  = ridx >> 3;
            int ci = ridx & 7;
            int gh = h0 + r - 1;
            uint32_t v = 0;
            if ((unsigned)gh < (unsigned)HW)
                v = inb[((ci0 + ci) * HW + gh) * HW + lcol];
            s_in[ridx * 72 + lcol + 1] = v;
        }
        // ---- weight chunk: 72 rows (t*8+ci) x 64 cols ----
        #pragma unroll
        for (int p = 0; p < 18; p++) {
            int ridx = p * 4 + lrow;          // 0..71
            int t  = ridx >> 3;
            int ci = ridx & 7;
            s_w[ridx * 72 + lcol] =
                __float_as_uint(wp[((size_t)(ci0 + ci) * 9 + t) * Cout + co0 + lcol]);
        }
        __syncthreads();

        #pragma unroll
        for (int t = 0; t < 9; t++) {
            const int kh = t / 3, kw = t % 3;
            uint32_t a[2][4];
            #pragma unroll
            for (int mt = 0; mt < 2; mt++) {
                int base = co_w + mt * 16;
                a[mt][0] = s_w[(t * 8 + tg) * 72 + base + g];
                a[mt][1] = s_w[(t * 8 + tg) * 72 + base + g + 8];
                a[mt][2] = s_w[(t * 8 + tg + 4) * 72 + base + g];
                a[mt][3] = s_w[(t * 8 + tg + 4) * 72 + base + g + 8];
            }
            const int rr = r_w + kh;
            #pragma unroll
            for (int nt = 0; nt < 8; nt++) {
                int c = nt * 8 + g + kw;
                uint32_t b0 = s_in[(rr * 8 + tg) * 72 + c];
                uint32_t b1 = s_in[(rr * 8 + tg + 4) * 72 + c];
                mma_tf32(acc[0][nt], a[0], b0, b1);
                mma_tf32(acc[1][nt], a[1], b0, b1);
            }
        }
        __syncthreads();
    }

    // ---- epilogue: BN + SiLU, store tf32 bits ----
    const int h = h0 + r_w;
    #pragma unroll
    for (int mt = 0; mt < 2; mt++) {
        int coA = co0 + co_w + mt * 16 + g;
        int coB = coA + 8;
        float scA = scale[coA], shA = shift[coA];
        float scB = scale[coB], shB = shift[coB];
        uint32_t* rowA = out + (((size_t)b * Cout + coA) * HW + h) * HW;
        uint32_t* rowB = out + (((size_t)b * Cout + coB) * HW + h) * HW;
        #pragma unroll
        for (int nt = 0; nt < 8; nt++) {
            int px = nt * 8 + tg * 2;
            uint2 vA, vB;
            vA.x = f2tf32(silu(acc[mt][nt][0] * scA + shA));
            vA.y = f2tf32(silu(acc[mt][nt][1] * scA + shA));
            vB.x = f2tf32(silu(acc[mt][nt][2] * scB + shB));
            vB.y = f2tf32(silu(acc[mt][nt][3] * scB + shB));
            *(uint2*)&rowA[px] = vA;
            *(uint2*)&rowB[px] = vB;
        }
    }
}

// ---------------- gram: scores[b] = (Q/T) Q^T, symmetric (10 of 16 tiles) ----------------
// Block tile 64c x 64d, K-chunk 32. 8 warps: warp tile 32c x 16d. Register prefetch.
__global__ void __launch_bounds__(256)
gram_mma(const uint32_t* __restrict__ y2, float* __restrict__ sc)
{
    const int b  = blockIdx.y;
    const int ti = c_ti[blockIdx.x];
    const int tj = c_tj[blockIdx.x];
    const int c0 = ti * 64, d0 = tj * 64;
    const int tid  = threadIdx.x;
    const int wid  = tid >> 5;
    const int lane = tid & 31;
    const int g  = lane >> 2;
    const int tg = lane & 3;
    const int m_w = (wid & 1) * 32;
    const int n_w = (wid >> 1) * 16;

    __shared__ uint32_t sA[64 * 36];   // [c][k], stride 36
    __shared__ uint32_t sB[64 * 36];   // [d][k]

    float acc[2][2][4];
    #pragma unroll
    for (int mt = 0; mt < 2; mt++)
        #pragma unroll
        for (int nt = 0; nt < 2; nt++)
            #pragma unroll
            for (int r = 0; r < 4; r++) acc[mt][nt][r] = 0.f;

    const uint32_t* Q = y2 + (size_t)b * C1 * NPIX;
    const int lrow = tid >> 3;        // 0..31
    const int lseg = (tid & 7) * 4;   // k offset

    uint4 pa[2], pb[2];
    {
        pa[0] = *(const uint4*)&Q[(size_t)(c0 + lrow)      * NPIX + lseg];
        pa[1] = *(const uint4*)&Q[(size_t)(c0 + lrow + 32) * NPIX + lseg];
        pb[0] = *(const uint4*)&Q[(size_t)(d0 + lrow)      * NPIX + lseg];
        pb[1] = *(const uint4*)&Q[(size_t)(d0 + lrow + 32) * NPIX + lseg];
    }

    for (int nk = 0; nk < NPIX; nk += 32) {
        __syncthreads();
        *(uint4*)&sA[lrow * 36 + lseg]        = pa[0];
        *(uint4*)&sA[(lrow + 32) * 36 + lseg] = pa[1];
        *(uint4*)&sB[lrow * 36 + lseg]        = pb[0];
        *(uint4*)&sB[(lrow + 32) * 36 + lseg] = pb[1];
        __syncthreads();

        int nk2 = nk + 32;
        if (nk2 < NPIX) {
            pa[0] = *(const uint4*)&Q[(size_t)(c0 + lrow)      * NPIX + nk2 + lseg];
            pa[1] = *(const uint4*)&Q[(size_t)(c0 + lrow + 32) * NPIX + nk2 + lseg];
            pb[0] = *(const uint4*)&Q[(size_t)(d0 + lrow)      * NPIX + nk2 + lseg];
            pb[1] = *(const uint4*)&Q[(size_t)(d0 + lrow + 32) * NPIX + nk2 + lseg];
        }

        #pragma unroll
        for (int ks = 0; ks < 4; ks++) {
            int kb = ks * 8;
            uint32_t a[2][4];
            #pragma unroll
            for (int mt = 0; mt < 2; mt++) {
                int base = m_w + mt * 16;
                a[mt][0] = sA[(base + g) * 36 + kb + tg];
                a[mt][1] = sA[(base + g + 8) * 36 + kb + tg];
                a[mt][2] = sA[(base + g) * 36 + kb + tg + 4];
                a[mt][3] = sA[(base + g + 8) * 36 + kb + tg + 4];
            }
            #pragma unroll
            for (int nt = 0; nt < 2; nt++) {
                uint32_t b0 = sB[(n_w + nt * 8 + g) * 36 + kb + tg];
                uint32_t b1 = sB[(n_w + nt * 8 + g) * 36 + kb + tg + 4];
                mma_tf32(acc[0][nt], a[0], b0, b1);
                mma_tf32(acc[1][nt], a[1], b0, b1);
            }
        }
    }

    const bool mirror = (ti != tj);
    #pragma unroll
    for (int mt = 0; mt < 2; mt++) {
        int cA = c0 + m_w + mt * 16 + g;
        int cB = cA + 8;
        #pragma unroll
        for (int nt = 0; nt < 2; nt++) {
            int d = d0 + n_w + nt * 8 + tg * 2;
            float v0 = acc[mt][nt][0] * INV_T;
            float v1 = acc[mt][nt][1] * INV_T;
            float v2 = acc[mt][nt][2] * INV_T;
            float v3 = acc[mt][nt][3] * INV_T;
            *(float2*)&sc[((size_t)b * C1 + cA) * C1 + d] = make_float2(v0, v1);
            *(float2*)&sc[((size_t)b * C1 + cB) * C1 + d] = make_float2(v2, v3);
            if (mirror) {
                sc[((size_t)b * C1 + d)     * C1 + cA] = v0;
                sc[((size_t)b * C1 + d + 1) * C1 + cA] = v1;
                sc[((size_t)b * C1 + d)     * C1 + cB] = v2;
                sc[((size_t)b * C1 + d + 1) * C1 + cB] = v3;
            }
        }
    }
}

// ---------------- softmax: warp per row of 256 ----------------
__global__ void __launch_bounds__(256)
softmax256(float* __restrict__ sc)
{
    const int row  = blockIdx.x * 8 + (threadIdx.x >> 5);
    const int lane = threadIdx.x & 31;
    float* p = sc + (size_t)row * C1;

    float4 v0 = *(const float4*)&p[lane * 4];
    float4 v1 = *(const float4*)&p[128 + lane * 4];

    float m = fmaxf(fmaxf(fmaxf(v0.x, v0.y), fmaxf(v0.z, v0.w)),
                    fmaxf(fmaxf(v1.x, v1.y), fmaxf(v1.z, v1.w)));
    #pragma unroll
    for (int s = 16; s > 0; s >>= 1)
        m = fmaxf(m, __shfl_xor_sync(0xffffffffu, m, s));

    v0.x = __expf(v0.x - m); v0.y = __expf(v0.y - m);
    v0.z = __expf(v0.z - m); v0.w = __expf(v0.w - m);
    v1.x = __expf(v1.x - m); v1.y = __expf(v1.y - m);
    v1.z = __expf(v1.z - m); v1.w = __expf(v1.w - m);

    float s8 = v0.x + v0.y + v0.z + v0.w + v1.x + v1.y + v1.z + v1.w;
    #pragma unroll
    for (int s = 16; s > 0; s >>= 1)
        s8 += __shfl_xor_sync(0xffffffffu, s8, s);

    float inv = 1.0f / s8;
    v0.x *= inv; v0.y *= inv; v0.z *= inv; v0.w *= inv;
    v1.x *= inv; v1.y *= inv; v1.z *= inv; v1.w *= inv;

    *(float4*)&p[lane * 4]       = v0;
    *(float4*)&p[128 + lane * 4] = v1;
}

// ---------------- out[b] = attn[b] @ Q[b] + x ----------------
// Block tile 64c x 128n, K-chunk 32 (8 chunks). 8 warps: warp tile 32c x 32n.
__global__ void __launch_bounds__(256)
attn_out_mma(const float* __restrict__ attn, const uint32_t* __restrict__ y2,
             const float* __restrict__ x, float* __restrict__ out)
{
    const int b  = blockIdx.z;
    const int c0 = blockIdx.y * 64;
    const int n0 = blockIdx.x * 128;
    const int tid  = threadIdx.x;
    const int wid  = tid >> 5;
    const int lane = tid & 31;
    const int g  = lane >> 2;
    const int tg = lane & 3;
    const int m_w = (wid & 1) * 32;
    const int n_w = (wid >> 1) * 32;

    __shared__ uint32_t sA[64 * 36];    // [c][k] stride 36
    __shared__ uint32_t sB[32 * 136];   // [k][n] stride 136

    float acc[2][4][4];
    #pragma unroll
    for (int mt = 0; mt < 2; mt++)
        #pragma unroll
        for (int nt = 0; nt < 4; nt++)
            #pragma unroll
            for (int r = 0; r < 4; r++) acc[mt][nt][r] = 0.f;

    const float* A = attn + (size_t)b * C1 * C1;
    const uint32_t* Q = y2 + (size_t)b * C1 * NPIX;

    const int arow = tid >> 3;         // 0..31
    const int aseg = (tid & 7) * 4;
    const int brow = tid >> 5;         // 0..7
    const int bseg = (tid & 31) * 4;

    float4 pa[2];
    uint4  pb[4];
    {
        pa[0] = *(const float4*)&A[(size_t)(c0 + arow) * C1 + aseg];
        pa[1] = *(const float4*)&A[(size_t)(c0 + arow + 32) * C1 + aseg];
        #pragma unroll
        for (int p = 0; p < 4; p++)
            pb[p] = *(const uint4*)&Q[(size_t)(brow + p * 8) * NPIX + n0 + bseg];
    }

    for (int dk = 0; dk < C1; dk += 32) {
        __syncthreads();
        {
            uint4 u;
            u.x = f2tf32(pa[0].x); u.y = f2tf32(pa[0].y);
            u.z = f2tf32(pa[0].z); u.w = f2tf32(pa[0].w);
            *(uint4*)&sA[arow * 36 + aseg] = u;
            u.x = f2tf32(pa[1].x); u.y = f2tf32(pa[1].y);
            u.z = f2tf32(pa[1].z); u.w = f2tf32(pa[1].w);
            *(uint4*)&sA[(arow + 32) * 36 + aseg] = u;
            #pragma unroll
            for (int p = 0; p < 4; p++)
                *(uint4*)&sB[(brow + p * 8) * 136 + bseg] = pb[p];
        }
        __syncthreads();

        int dk2 = dk + 32;
        if (dk2 < C1) {
            pa[0] = *(const float4*)&A[(size_t)(c0 + arow) * C1 + dk2 + aseg];
            pa[1] = *(const float4*)&A[(size_t)(c0 + arow + 32) * C1 + dk2 + aseg];
            #pragma unroll
            for (int p = 0; p < 4; p++)
                pb[p] = *(const uint4*)&Q[(size_t)(dk2 + brow + p * 8) * NPIX + n0 + bseg];
        }

        #pragma unroll
        for (int ks = 0; ks < 4; ks++) {
            int kb = ks * 8;
            uint32_t a[2][4];
            #pragma unroll
            for (int mt = 0; mt < 2; mt++) {
                int base = m_w + mt * 16;
                a[mt][0] = sA[(base + g) * 36 + kb + tg];
                a[mt][1] = sA[(base + g + 8) * 36 + kb + tg];
                a[mt][2] = sA[(base + g) * 36 + kb + tg + 4];
                a[mt][3] = sA[(base + g + 8) * 36 + kb + tg + 4];
            }
            #pragma unroll
            for (int nt = 0; nt < 4; nt++) {
                int nn = n_w + nt * 8 + g;
                uint32_t b0 = sB[(kb + tg) * 136 + nn];
                uint32_t b1 = sB[(kb + tg + 4) * 136 + nn];
                mma_tf32(acc[0][nt], a[0], b0, b1);
                mma_tf32(acc[1][nt], a[1], b0, b1);
            }
        }
    }

    #pragma unroll
    for (int mt = 0; mt < 2; mt++) {
        int cA = c0 + m_w + mt * 16 + g;
        int cB = cA + 8;
        #pragma unroll
        for (int nt = 0; nt < 4; nt++) {
            int n = n0 + n_w + nt * 8 + tg * 2;
            size_t iA = ((size_t)b * C1 + cA) * NPIX + n;
            size_t iB = ((size_t)b * C1 + cB) * NPIX + n;
            float2 xA = *(const float2*)&x[iA];
            float2 xB = *(const float2*)&x[iB];
            *(float2*)&out[iA] = make_float2(acc[mt][nt][0] + xA.x, acc[mt][nt][1] + xA.y);
            *(float2*)&out[iB] = make_float2(acc[mt][nt][2] + xB.x, acc[mt][nt][3] + xB.y);
        }
    }
}

// ---------------- launch ----------------
extern "C" void kernel_launch(void* const* d_in, const int* in_sizes, int n_in,
                              void* d_out, int out_size)
{
    const float* x  = (const float*)d_in[0];
    const float* w1 = (const float*)d_in[1];
    const float* g1 = (const float*)d_in[2];
    const float* b1 = (const float*)d_in[3];
    const float* m1 = (const float*)d_in[4];
    const float* v1 = (const float*)d_in[5];
    const float* w2 = (const float*)d_in[6];
    const float* g2 = (const float*)d_in[7];
    const float* b2 = (const float*)d_in[8];
    const float* m2 = (const float*)d_in[9];
    const float* v2 = (const float*)d_in[10];
    float* out = (float*)d_out;

    uint32_t *xtp, *y1p, *y2p;
    float *scp, *w1p, *w2p, *sc1p, *sh1p, *sc2p, *sh2p;
    cudaGetSymbolAddress((void**)&xtp,  g_xt);
    cudaGetSymbolAddress((void**)&y1p,  g_y1);
    cudaGetSymbolAddress((void**)&y2p,  g_y2);
    cudaGetSymbolAddress((void**)&scp,  g_sc);
    cudaGetSymbolAddress((void**)&w1p,  g_w1p);
    cudaGetSymbolAddress((void**)&w2p,  g_w2p);
    cudaGetSymbolAddress((void**)&sc1p, g_scale1);
    cudaGetSymbolAddress((void**)&sh1p, g_shift1);
    cudaGetSymbolAddress((void**)&sc2p, g_scale2);
    cudaGetSymbolAddress((void**)&sh2p, g_shift2);

    fold_bn<<<1, 256>>>(g1, b1, m1, v1, g2, b2, m2, v2);

    int nw1 = CH * C1 * 9;
    repack_w<<<(nw1 + 255) / 256, 256>>>(w1, w1p, CH, C1);
    repack_w<<<(nw1 + 255) / 256, 256>>>(w2, w2p, C1, CH);

    int n4 = BATCH * C1 * NPIX / 4;
    cvt_to_tf32<<<(n4 + 255) / 256, 256>>>((const float4*)x, (uint4*)xtp, n4);

    conv3x3_mma<C1><<<dim3(CH / 64, HW / 4, BATCH), 256>>>(xtp, w1p, sc1p, sh1p, y1p, CH);
    conv3x3_mma<CH><<<dim3(C1 / 64, HW / 4, BATCH), 256>>>(y1p, w2p, sc2p, sh2p, y2p, C1);

    gram_mma<<<dim3(10, BATCH), 256>>>(y2p, scp);
    softmax256<<<BATCH * C1 / 8, 256>>>(scp);
    attn_out_mma<<<dim3(NPIX / 128, C1 / 64, BATCH), 256>>>(scp, y2p, x, out);
}

// round 10
// speedup vs baseline: 3.7183x; 1.2955x over previous
#include <cuda_runtime.h>
#include <cstdint>

// ---------------- problem constants ----------------
#define BATCH 16
#define C1    256
#define CH    128
#define HW    64
#define NPIX  (HW*HW)
#define INV_T (1.0f/16.0f)

// ---------------- scratch ----------------
__device__ uint32_t g_xt[BATCH * C1 * NPIX];   // x as tf32 bits
__device__ uint32_t g_y1[BATCH * CH * NPIX];   // y1 as tf32 bits
__device__ uint32_t g_y2[BATCH * C1 * NPIX];   // y2 as tf32 bits
__device__ float    g_sc[BATCH * C1 * C1];     // scores (fp32) -> attn (tf32 bits)
__device__ float    g_w1p[CH * C1 * 9];        // tf32-bit weights [ci][tap][co]
__device__ float    g_w2p[C1 * CH * 9];
__device__ float    g_scale1[CH], g_shift1[CH];
__device__ float    g_scale2[C1], g_shift2[C1];

__constant__ int c_ti[10] = {0,0,0,0,1,1,1,2,2,3};
__constant__ int c_tj[10] = {0,1,2,3,1,2,3,2,3,3};

// ---------------- helpers ----------------
__device__ __forceinline__ uint32_t f2tf32(float f) {
    uint32_t u;
    asm("cvt.rna.tf32.f32 %0, %1;" : "=r"(u) : "f"(f));
    return u;
}

__device__ __forceinline__ void mma_tf32(float c[4], const uint32_t a[4],
                                         uint32_t b0, uint32_t b1) {
    asm volatile(
        "mma.sync.aligned.m16n8k8.row.col.f32.tf32.tf32.f32 "
        "{%0,%1,%2,%3}, {%4,%5,%6,%7}, {%8,%9}, {%0,%1,%2,%3};"
        : "+f"(c[0]), "+f"(c[1]), "+f"(c[2]), "+f"(c[3])
        : "r"(a[0]), "r"(a[1]), "r"(a[2]), "r"(a[3]), "r"(b0), "r"(b1));
}

__device__ __forceinline__ float silu(float y) {
    return y / (1.0f + __expf(-y));
}

__device__ __forceinline__ uint32_t smem_u32(const void* p) {
    return (uint32_t)__cvta_generic_to_shared(p);
}
__device__ __forceinline__ void cp16(uint32_t dst, const void* src) {
    asm volatile("cp.async.cg.shared.global [%0], [%1], 16;" :: "r"(dst), "l"(src));
}
__device__ __forceinline__ void cp16z(uint32_t dst, const void* src, int sz) {
    asm volatile("cp.async.cg.shared.global [%0], [%1], 16, %2;" :: "r"(dst), "l"(src), "r"(sz));
}
__device__ __forceinline__ void cp_commit() { asm volatile("cp.async.commit_group;"); }
template<int N> __device__ __forceinline__ void cp_wait() {
    asm volatile("cp.async.wait_group %0;" :: "n"(N));
}

// ---------------- BN fold ----------------
__global__ void fold_bn(const float* __restrict__ g1, const float* __restrict__ b1,
                        const float* __restrict__ m1, const float* __restrict__ v1,
                        const float* __restrict__ g2, const float* __restrict__ b2,
                        const float* __restrict__ m2, const float* __restrict__ v2)
{
    int i = threadIdx.x;
    if (i < CH) {
        float s = g1[i] * rsqrtf(v1[i] + 1e-5f);
        g_scale1[i] = s;
        g_shift1[i] = b1[i] - m1[i] * s;
    }
    if (i < C1) {
        float s = g2[i] * rsqrtf(v2[i] + 1e-5f);
        g_scale2[i] = s;
        g_shift2[i] = b2[i] - m2[i] * s;
    }
}

// ---------------- weight repack: [co][ci][t] -> [ci][t][co], tf32 bits ----------------
__global__ void repack_w(const float* __restrict__ w, float* __restrict__ wp,
                         int Cout, int Cin)
{
    int i = blockIdx.x * 256 + threadIdx.x;
    int total = Cout * Cin * 9;
    if (i < total) {
        int co = i / (Cin * 9);
        int ci = (i / 9) % Cin;
        int t  = i % 9;
        wp[(ci * 9 + t) * Cout + co] = __uint_as_float(f2tf32(w[i]));
    }
}

// ---------------- bulk fp32 -> tf32 bits ----------------
__global__ void cvt_to_tf32(const float4* __restrict__ src, uint4* __restrict__ dst, int n4)
{
    int i = blockIdx.x * 256 + threadIdx.x;
    if (i < n4) {
        float4 v = src[i];
        uint4 u;
        u.x = f2tf32(v.x); u.y = f2tf32(v.y);
        u.z = f2tf32(v.z); u.w = f2tf32(v.w);
        dst[i] = u;
    }
}

// ---------------- conv 3x3 same + BN + SiLU  (tf32 mma, cp.async 2-stage) ----------------
// Block: 64 cout x 4 rows x 64 px. 8 warps: wid&1 -> co half, wid>>1 -> row.
// Warp tile: 32 cout x 64 px = 2 m-tiles x 8 n-tiles m16n8k8. K-chunk = 8 cin.
// s_in row layout: pixel gw stored at col gw+4 (cols 4..67); zero halo at cols 3 and 68.
template<int CIN>
__global__ void __launch_bounds__(256)
conv3x3_mma(const uint32_t* __restrict__ in, const float* __restrict__ wp,
            const float* __restrict__ scale, const float* __restrict__ shift,
            uint32_t* __restrict__ out, int Cout)
{
    const int b   = blockIdx.z;
    const int h0  = blockIdx.y * 4;
    const int co0 = blockIdx.x * 64;
    const int tid  = threadIdx.x;
    const int wid  = tid >> 5;
    const int lane = tid & 31;
    const int g  = lane >> 2;
    const int tg = lane & 3;
    const int co_w = (wid & 1) * 32;
    const int r_w  = wid >> 1;          // 0..3

    __shared__ uint32_t s_in[2][48 * 72];
    __shared__ uint32_t s_w[2][72 * 72];

    float acc[2][8][4];
    #pragma unroll
    for (int mt = 0; mt < 2; mt++)
        #pragma unroll
        for (int nt = 0; nt < 8; nt++)
            #pragma unroll
            for (int r = 0; r < 4; r++) acc[mt][nt][r] = 0.f;

    // zero halo cols (3, 68) for all 48 rows x both stages
    if (tid < 192) {
        int buf = tid / 96;
        int rem = tid % 96;
        int r   = rem >> 1;
        s_in[buf][r * 72 + ((rem & 1) ? 68 : 3)] = 0;
    }

    const uint32_t* inb = in + (size_t)b * CIN * NPIX;
    const uint32_t* wpb = (const uint32_t*)wp;

    const int e_row  = tid >> 4;        // 0..15
    const int e_cseg = (tid & 15) * 4;

    auto issue_chunk = [&](int ci0, int buf) {
        // input: 48 rows x 64 cols (16B ops, zero-fill for OOB rows)
        uint32_t in_base = smem_u32(&s_in[buf][0]);
        #pragma unroll
        for (int p = 0; p < 3; p++) {
            int ridx = p * 16 + e_row;            // 0..47
            int r  = ridx >> 3;
            int ci = ridx & 7;
            int gh = h0 + r - 1;
            bool valid = (unsigned)gh < (unsigned)HW;
            int ghc = valid ? gh : 0;
            const uint32_t* src = inb + ((ci0 + ci) * HW + ghc) * HW + e_cseg;
            cp16z(in_base + (ridx * 72 + 4 + e_cseg) * 4, src, valid ? 16 : 0);
        }
        // weights: 72 rows (t*8+ci) x 64 cols
        uint32_t w_base = smem_u32(&s_w[buf][0]);
        #pragma unroll
        for (int p = 0; p < 5; p++) {
            int ridx = p * 16 + e_row;            // 0..79, guard <72
            if (ridx < 72) {
                int t  = ridx >> 3;
                int ci = ridx & 7;
                const uint32_t* src = wpb + ((size_t)(ci0 + ci) * 9 + t) * Cout + co0 + e_cseg;
                cp16(w_base + (ridx * 72 + e_cseg) * 4, src);
            }
        }
    };

    const int NCH = CIN / 8;
    issue_chunk(0, 0);
    cp_commit();

    for (int c = 0; c < NCH; c++) {
        if (c + 1 < NCH) {
            issue_chunk((c + 1) * 8, (c + 1) & 1);
            cp_commit();
            cp_wait<1>();
        } else {
            cp_wait<0>();
        }
        __syncthreads();

        const uint32_t* si = s_in[c & 1];
        const uint32_t* sw = s_w[c & 1];

        #pragma unroll
        for (int t = 0; t < 9; t++) {
            const int kh = t / 3, kw = t % 3;
            uint32_t a[2][4];
            #pragma unroll
            for (int mt = 0; mt < 2; mt++) {
                int base = co_w + mt * 16;
                a[mt][0] = sw[(t * 8 + tg) * 72 + base + g];
                a[mt][1] = sw[(t * 8 + tg) * 72 + base + g + 8];
                a[mt][2] = sw[(t * 8 + tg + 4) * 72 + base + g];
                a[mt][3] = sw[(t * 8 + tg + 4) * 72 + base + g + 8];
            }
            const int rr = r_w + kh;
            #pragma unroll
            for (int nt = 0; nt < 8; nt++) {
                int col = 3 + nt * 8 + g + kw;   // gw = px+kw-1 stored at gw+4 = px+kw+3
                uint32_t b0 = si[(rr * 8 + tg) * 72 + col];
                uint32_t b1 = si[(rr * 8 + tg + 4) * 72 + col];
                mma_tf32(acc[0][nt], a[0], b0, b1);
                mma_tf32(acc[1][nt], a[1], b0, b1);
            }
        }
        __syncthreads();
    }

    // ---- epilogue: BN + SiLU, store tf32 bits ----
    const int h = h0 + r_w;
    #pragma unroll
    for (int mt = 0; mt < 2; mt++) {
        int coA = co0 + co_w + mt * 16 + g;
        int coB = coA + 8;
        float scA = scale[coA], shA = shift[coA];
        float scB = scale[coB], shB = shift[coB];
        uint32_t* rowA = out + (((size_t)b * Cout + coA) * HW + h) * HW;
        uint32_t* rowB = out + (((size_t)b * Cout + coB) * HW + h) * HW;
        #pragma unroll
        for (int nt = 0; nt < 8; nt++) {
            int px = nt * 8 + tg * 2;
            uint2 vA, vB;
            vA.x = f2tf32(silu(acc[mt][nt][0] * scA + shA));
            vA.y = f2tf32(silu(acc[mt][nt][1] * scA + shA));
            vB.x = f2tf32(silu(acc[mt][nt][2] * scB + shB));
            vB.y = f2tf32(silu(acc[mt][nt][3] * scB + shB));
            *(uint2*)&rowA[px] = vA;
            *(uint2*)&rowB[px] = vB;
        }
    }
}

// ---------------- gram: scores[b] = (Q/T) Q^T, symmetric, cp.async 2-stage ----------------
__global__ void __launch_bounds__(256)
gram_mma(const uint32_t* __restrict__ y2, float* __restrict__ sc)
{
    const int b  = blockIdx.y;
    const int ti = c_ti[blockIdx.x];
    const int tj = c_tj[blockIdx.x];
    const int c0 = ti * 64, d0 = tj * 64;
    const int tid  = threadIdx.x;
    const int wid  = tid >> 5;
    const int lane = tid & 31;
    const int g  = lane >> 2;
    const int tg = lane & 3;
    const int m_w = (wid & 1) * 32;
    const int n_w = (wid >> 1) * 16;

    __shared__ uint32_t sA[2][64 * 36];   // [c][k]
    __shared__ uint32_t sB[2][64 * 36];   // [d][k]

    float acc[2][2][4];
    #pragma unroll
    for (int mt = 0; mt < 2; mt++)
        #pragma unroll
        for (int nt = 0; nt < 2; nt++)
            #pragma unroll
            for (int r = 0; r < 4; r++) acc[mt][nt][r] = 0.f;

    const uint32_t* Q = y2 + (size_t)b * C1 * NPIX;
    const int e_row  = tid >> 3;          // 0..31
    const int e_kseg = (tid & 7) * 4;

    auto issue_chunk = [&](int nk, int buf) {
        uint32_t a_base = smem_u32(&sA[buf][0]);
        uint32_t b_base = smem_u32(&sB[buf][0]);
        #pragma unroll
        for (int p = 0; p < 2; p++) {
            int row = p * 32 + e_row;  // 0..63
            cp16(a_base + (row * 36 + e_kseg) * 4, Q + (size_t)(c0 + row) * NPIX + nk + e_kseg);
            cp16(b_base + (row * 36 + e_kseg) * 4, Q + (size_t)(d0 + row) * NPIX + nk + e_kseg);
        }
    };

    issue_chunk(0, 0);
    cp_commit();

    const int NCH = NPIX / 32;
    for (int c = 0; c < NCH; c++) {
        if (c + 1 < NCH) {
            issue_chunk((c + 1) * 32, (c + 1) & 1);
            cp_commit();
            cp_wait<1>();
        } else {
            cp_wait<0>();
        }
        __syncthreads();

        const uint32_t* a_s = sA[c & 1];
        const uint32_t* b_s = sB[c & 1];

        #pragma unroll
        for (int ks = 0; ks < 4; ks++) {
            int kb = ks * 8;
            uint32_t a[2][4];
            #pragma unroll
            for (int mt = 0; mt < 2; mt++) {
                int base = m_w + mt * 16;
                a[mt][0] = a_s[(base + g) * 36 + kb + tg];
                a[mt][1] = a_s[(base + g + 8) * 36 + kb + tg];
                a[mt][2] = a_s[(base + g) * 36 + kb + tg + 4];
                a[mt][3] = a_s[(base + g + 8) * 36 + kb + tg + 4];
            }
            #pragma unroll
            for (int nt = 0; nt < 2; nt++) {
                uint32_t b0 = b_s[(n_w + nt * 8 + g) * 36 + kb + tg];
                uint32_t b1 = b_s[(n_w + nt * 8 + g) * 36 + kb + tg + 4];
                mma_tf32(acc[0][nt], a[0], b0, b1);
                mma_tf32(acc[1][nt], a[1], b0, b1);
            }
        }
        __syncthreads();
    }

    const bool mirror = (ti != tj);
    #pragma unroll
    for (int mt = 0; mt < 2; mt++) {
        int cA = c0 + m_w + mt * 16 + g;
        int cB = cA + 8;
        #pragma unroll
        for (int nt = 0; nt < 2; nt++) {
            int d = d0 + n_w + nt * 8 + tg * 2;
            float v0 = acc[mt][nt][0] * INV_T;
            float v1 = acc[mt][nt][1] * INV_T;
            float v2 = acc[mt][nt][2] * INV_T;
            float v3 = acc[mt][nt][3] * INV_T;
            *(float2*)&sc[((size_t)b * C1 + cA) * C1 + d] = make_float2(v0, v1);
            *(float2*)&sc[((size_t)b * C1 + cB) * C1 + d] = make_float2(v2, v3);
            if (mirror) {
                sc[((size_t)b * C1 + d)     * C1 + cA] = v0;
                sc[((size_t)b * C1 + d + 1) * C1 + cA] = v1;
                sc[((size_t)b * C1 + d)     * C1 + cB] = v2;
                sc[((size_t)b * C1 + d + 1) * C1 + cB] = v3;
            }
        }
    }
}

// ---------------- softmax: warp per row of 256, writes tf32 bits in place ----------------
__global__ void __launch_bounds__(256)
softmax256(float* __restrict__ sc)
{
    const int row  = blockIdx.x * 8 + (threadIdx.x >> 5);
    const int lane = threadIdx.x & 31;
    float* p = sc + (size_t)row * C1;

    float4 v0 = *(const float4*)&p[lane * 4];
    float4 v1 = *(const float4*)&p[128 + lane * 4];

    float m = fmaxf(fmaxf(fmaxf(v0.x, v0.y), fmaxf(v0.z, v0.w)),
                    fmaxf(fmaxf(v1.x, v1.y), fmaxf(v1.z, v1.w)));
    #pragma unroll
    for (int s = 16; s > 0; s >>= 1)
        m = fmaxf(m, __shfl_xor_sync(0xffffffffu, m, s));

    v0.x = __expf(v0.x - m); v0.y = __expf(v0.y - m);
    v0.z = __expf(v0.z - m); v0.w = __expf(v0.w - m);
    v1.x = __expf(v1.x - m); v1.y = __expf(v1.y - m);
    v1.z = __expf(v1.z - m); v1.w = __expf(v1.w - m);

    float s8 = v0.x + v0.y + v0.z + v0.w + v1.x + v1.y + v1.z + v1.w;
    #pragma unroll
    for (int s = 16; s > 0; s >>= 1)
        s8 += __shfl_xor_sync(0xffffffffu, s8, s);

    float inv = 1.0f / s8;
    uint4 u0, u1;
    u0.x = f2tf32(v0.x * inv); u0.y = f2tf32(v0.y * inv);
    u0.z = f2tf32(v0.z * inv); u0.w = f2tf32(v0.w * inv);
    u1.x = f2tf32(v1.x * inv); u1.y = f2tf32(v1.y * inv);
    u1.z = f2tf32(v1.z * inv); u1.w = f2tf32(v1.w * inv);

    *(uint4*)&p[lane * 4]       = u0;
    *(uint4*)&p[128 + lane * 4] = u1;
}

// ---------------- out[b] = attn[b] @ Q[b] + x, cp.async 2-stage ----------------
// Block tile 64c x 128n, K-chunk 32. 8 warps: warp tile 32c x 32n.
__global__ void __launch_bounds__(256)
attn_out_mma(const uint32_t* __restrict__ attn, const uint32_t* __restrict__ y2,
             const float* __restrict__ x, float* __restrict__ out)
{
    const int b  = blockIdx.z;
    const int c0 = blockIdx.y * 64;
    const int n0 = blockIdx.x * 128;
    const int tid  = threadIdx.x;
    const int wid  = tid >> 5;
    const int lane = tid & 31;
    const int g  = lane >> 2;
    const int tg = lane & 3;
    const int m_w = (wid & 1) * 32;
    const int n_w = (wid >> 1) * 32;

    __shared__ uint32_t sA[2][64 * 36];    // [c][k]
    __shared__ uint32_t sB[2][32 * 136];   // [k][n]

    float acc[2][4][4];
    #pragma unroll
    for (int mt = 0; mt < 2; mt++)
        #pragma unroll
        for (int nt = 0; nt < 4; nt++)
            #pragma unroll
            for (int r = 0; r < 4; r++) acc[mt][nt][r] = 0.f;

    const uint32_t* A = attn + (size_t)b * C1 * C1;
    const uint32_t* Q = y2 + (size_t)b * C1 * NPIX;

    const int a_row  = tid >> 3;          // 0..31
    const int a_kseg = (tid & 7) * 4;
    const int b_row  = tid >> 5;          // 0..7
    const int b_nseg = (tid & 31) * 4;

    auto issue_chunk = [&](int dk, int buf) {
        uint32_t a_base = smem_u32(&sA[buf][0]);
        uint32_t b_base = smem_u32(&sB[buf][0]);
        #pragma unroll
        for (int p = 0; p < 2; p++) {
            int row = p * 32 + a_row;
            cp16(a_base + (row * 36 + a_kseg) * 4, A + (size_t)(c0 + row) * C1 + dk + a_kseg);
        }
        #pragma unroll
        for (int p = 0; p < 4; p++) {
            int row = p * 8 + b_row;
            cp16(b_base + (row * 136 + b_nseg) * 4, Q + (size_t)(dk + row) * NPIX + n0 + b_nseg);
        }
    };

    issue_chunk(0, 0);
    cp_commit();

    const int NCH = C1 / 32;
    for (int c = 0; c < NCH; c++) {
        if (c + 1 < NCH) {
            issue_chunk((c + 1) * 32, (c + 1) & 1);
            cp_commit();
            cp_wait<1>();
        } else {
            cp_wait<0>();
        }
        __syncthreads();

        const uint32_t* a_s = sA[c & 1];
        const uint32_t* b_s = sB[c & 1];

        #pragma unroll
        for (int ks = 0; ks < 4; ks++) {
            int kb = ks * 8;
            uint32_t a[2][4];
            #pragma unroll
            for (int mt = 0; mt < 2; mt++) {
                int base = m_w + mt * 16;
                a[mt][0] = a_s[(base + g) * 36 + kb + tg];
                a[mt][1] = a_s[(base + g + 8) * 36 + kb + tg];
                a[mt][2] = a_s[(base + g) * 36 + kb + tg + 4];
                a[mt][3] = a_s[(base + g + 8) * 36 + kb + tg + 4];
            }
            #pragma unroll
            for (int nt = 0; nt < 4; nt++) {
                int nn = n_w + nt * 8 + g;
                uint32_t b0 = b_s[(kb + tg) * 136 + nn];
                uint32_t b1 = b_s[(kb + tg + 4) * 136 + nn];
                mma_tf32(acc[0][nt], a[0], b0, b1);
                mma_tf32(acc[1][nt], a[1], b0, b1);
            }
        }
        __syncthreads();
    }

    #pragma unroll
    for (int mt = 0; mt < 2; mt++) {
        int cA = c0 + m_w + mt * 16 + g;
        int cB = cA + 8;
        #pragma unroll
        for (int nt = 0; nt < 4; nt++) {
            int n = n0 + n_w + nt * 8 + tg * 2;
            size_t iA = ((size_t)b * C1 + cA) * NPIX + n;
            size_t iB = ((size_t)b * C1 + cB) * NPIX + n;
            float2 xA = *(const float2*)&x[iA];
            float2 xB = *(const float2*)&x[iB];
            *(float2*)&out[iA] = make_float2(acc[mt][nt][0] + xA.x, acc[mt][nt][1] + xA.y);
            *(float2*)&out[iB] = make_float2(acc[mt][nt][2] + xB.x, acc[mt][nt][3] + xB.y);
        }
    }
}

// ---------------- launch ----------------
extern "C" void kernel_launch(void* const* d_in, const int* in_sizes, int n_in,
                              void* d_out, int out_size)
{
    const float* x  = (const float*)d_in[0];
    const float* w1 = (const float*)d_in[1];
    const float* g1 = (const float*)d_in[2];
    const float* b1 = (const float*)d_in[3];
    const float* m1 = (const float*)d_in[4];
    const float* v1 = (const float*)d_in[5];
    const float* w2 = (const float*)d_in[6];
    const float* g2 = (const float*)d_in[7];
    const float* b2 = (const float*)d_in[8];
    const float* m2 = (const float*)d_in[9];
    const float* v2 = (const float*)d_in[10];
    float* out = (float*)d_out;

    uint32_t *xtp, *y1p, *y2p;
    float *scp, *w1p, *w2p, *sc1p, *sh1p, *sc2p, *sh2p;
    cudaGetSymbolAddress((void**)&xtp,  g_xt);
    cudaGetSymbolAddress((void**)&y1p,  g_y1);
    cudaGetSymbolAddress((void**)&y2p,  g_y2);
    cudaGetSymbolAddress((void**)&scp,  g_sc);
    cudaGetSymbolAddress((void**)&w1p,  g_w1p);
    cudaGetSymbolAddress((void**)&w2p,  g_w2p);
    cudaGetSymbolAddress((void**)&sc1p, g_scale1);
    cudaGetSymbolAddress((void**)&sh1p, g_shift1);
    cudaGetSymbolAddress((void**)&sc2p, g_scale2);
    cudaGetSymbolAddress((void**)&sh2p, g_shift2);

    fold_bn<<<1, 256>>>(g1, b1, m1, v1, g2, b2, m2, v2);

    int nw1 = CH * C1 * 9;
    repack_w<<<(nw1 + 255) / 256, 256>>>(w1, w1p, CH, C1);
    repack_w<<<(nw1 + 255) / 256, 256>>>(w2, w2p, C1, CH);

    int n4 = BATCH * C1 * NPIX / 4;
    cvt_to_tf32<<<(n4 + 255) / 256, 256>>>((const float4*)x, (uint4*)xtp, n4);

    conv3x3_mma<C1><<<dim3(CH / 64, HW / 4, BATCH), 256>>>(xtp, w1p, sc1p, sh1p, y1p, CH);
    conv3x3_mma<CH><<<dim3(C1 / 64, HW / 4, BATCH), 256>>>(y1p, w2p, sc2p, sh2p, y2p, C1);

    gram_mma<<<dim3(10, BATCH), 256>>>(y2p, scp);
    softmax256<<<BATCH * C1 / 8, 256>>>(scp);
    attn_out_mma<<<dim3(NPIX / 128, C1 / 64, BATCH), 256>>>((const uint32_t*)scp, y2p, x, out);
}